// round 8
// baseline (speedup 1.0000x reference)
#include <cuda_runtime.h>
#include <cstdint>

// ContourIntegrationLayer: depthwise 3x3 conv (center tap zeroed) + residual.
// x: [B=32, H=56, W=56, C=256] fp32 NHWC, kernel: [3,3,256] fp32.
// Residual folded by forcing the center weight to 1.0.
//
// Round 8: cp.async (LDGSTS) 6-slot SMEM row ring, private per-thread slots:
// pipeline depth lives in commit-groups instead of registers -> 5 rows
// (20 x 16B) in flight per thread with no register cost and NO barriers
// (each thread consumes only data it staged itself; wait_group suffices).
// OOB rows / w-halos are cp.async'd from a zero buffer (L2-hot) so every
// iteration commits exactly one full group and `wait_group 5` is exact.
// Block: (8 channel-float4, 28 w-pairs) = 224 threads, occ 2.
// Grid:  8 channel-blocks x 4 H-chunks x 32 batches = 1024 blocks.

#define B_  32
#define H_  56
#define W_  56
#define C_  256
#define CG  8
#define HC  14                    // output rows per block
#define CQ  (C_ / 4)              // 64 float4 per pixel
#define ROWF4 (W_ * CQ)           // 3584 float4 per image row
#define S_  6                     // ring slots
#define NT  224                   // threads per block
#define SMEM_BYTES (S_ * 4 * NT * 16)   // 86016 B

__device__ __align__(16) float g_zero4[4] = {0.f, 0.f, 0.f, 0.f};

__device__ __forceinline__ void cp16(uint32_t dst, const void* src) {
    asm volatile("cp.async.cg.shared.global [%0], [%1], 16;"
                 :: "r"(dst), "l"(src));
}
__device__ __forceinline__ void cp_commit() {
    asm volatile("cp.async.commit_group;");
}
__device__ __forceinline__ void cp_wait5() {
    asm volatile("cp.async.wait_group 5;" ::: "memory");
}

extern __shared__ float4 sbuf[];          // [S_][4][NT]

__global__ __launch_bounds__(224, 2)
void contour_kernel(const float4* __restrict__ x,
                    const float*  __restrict__ krn,
                    float4*       __restrict__ out)
{
    const int tx  = threadIdx.x;          // 0..7  channel group
    const int ty  = threadIdx.y;          // 0..27 w-pair
    const int tid = ty * CG + tx;         // 0..223
    const int cb  = blockIdx.x;           // channel block
    const int hch = blockIdx.y;           // H chunk
    const int b   = blockIdx.z;           // batch
    const int c   = cb * 32 + tx * 4;

    // 3x3 per-channel weights; center tap := 1.0 (residual fold)
    float4 Wt[3][3];
#pragma unroll
    for (int ky = 0; ky < 3; ky++)
#pragma unroll
        for (int kx = 0; kx < 3; kx++)
            Wt[ky][kx] = *reinterpret_cast<const float4*>(krn + (ky * 3 + kx) * C_ + c);
    Wt[1][1] = make_float4(1.f, 1.f, 1.f, 1.f);

    const int  w0  = ty * 2;
    const bool wlo = (w0 > 0);
    const bool whi = (w0 + 2 < W_);
    const float4 z = make_float4(0.f, 0.f, 0.f, 0.f);

    const size_t base = (size_t)b * H_ * ROWF4 + (size_t)w0 * CQ + cb * CG + tx;
    const float4* xb = x   + base;
    float4*       ob = out + base;
    const float4* zp = (const float4*)g_zero4;

    const uint32_t sb  = (uint32_t)__cvta_generic_to_shared(sbuf) + tid * 16u;
    const int hs = hch * HC;

    // stage row r's 4 halo columns into ring slot (one commit group)
    auto load_async = [&](int r, int slot) {
        const bool rv = (unsigned)r < (unsigned)H_;
        const float4* p = xb + (size_t)(rv ? r : 0) * ROWF4;
        const uint32_t sa = sb + (uint32_t)(slot * 4 * NT) * 16u;
        cp16(sa,               (rv && wlo) ? p - CQ     : zp);
        cp16(sa + NT * 16u,     rv         ? p          : zp);
        cp16(sa + 2 * NT * 16u, rv         ? p + CQ     : zp);
        cp16(sa + 3 * NT * 16u, (rv && whi) ? p + 2 * CQ : zp);
        cp_commit();
    };

    // horizontal conv of v[0..3] with weight row k, accumulated into (o0,o1)
    auto hconv = [&](float4& o0, float4& o1, const float4 k0, const float4 k1,
                     const float4 k2, const float4* v) {
        o0.x = fmaf(k0.x, v[0].x, fmaf(k1.x, v[1].x, fmaf(k2.x, v[2].x, o0.x)));
        o0.y = fmaf(k0.y, v[0].y, fmaf(k1.y, v[1].y, fmaf(k2.y, v[2].y, o0.y)));
        o0.z = fmaf(k0.z, v[0].z, fmaf(k1.z, v[1].z, fmaf(k2.z, v[2].z, o0.z)));
        o0.w = fmaf(k0.w, v[0].w, fmaf(k1.w, v[1].w, fmaf(k2.w, v[2].w, o0.w)));
        o1.x = fmaf(k0.x, v[1].x, fmaf(k1.x, v[2].x, fmaf(k2.x, v[3].x, o1.x)));
        o1.y = fmaf(k0.y, v[1].y, fmaf(k1.y, v[2].y, fmaf(k2.y, v[3].y, o1.y)));
        o1.z = fmaf(k0.z, v[1].z, fmaf(k1.z, v[2].z, fmaf(k2.z, v[3].z, o1.z)));
        o1.w = fmaf(k0.w, v[1].w, fmaf(k1.w, v[2].w, fmaf(k2.w, v[3].w, o1.w)));
    };

    float4 am0 = z, am1 = z;      // partial accum for output row r-1
    float4 ac0 = z, ac1 = z;      // partial accum for output row r

    // prolog: stage rows hs-1 .. hs+4 into slots 0..5 (6 groups)
    load_async(hs - 1, 0);
    load_async(hs,     1);
    load_async(hs + 1, 2);
    load_async(hs + 2, 3);
    load_async(hs + 3, 4);
    load_async(hs + 4, 5);

    // iterations i = 0..HC+1 consume input rows hs-1 .. hs+HC.
    // Group accounting: issued = 6+i before iteration i's refill; wait_group 5
    // leaves <=5 pending -> the (i+1)-th group (slot i%6's writer) is done.
#pragma unroll
    for (int i = 0; i < HC + 2; i++) {
        const int r = hs - 1 + i;
        const int slot = i % S_;

        cp_wait5();
        const float4* pl = sbuf + slot * 4 * NT + tid;
        float4 cur[4];
        cur[0] = pl[0];
        cur[1] = pl[NT];
        cur[2] = pl[2 * NT];
        cur[3] = pl[3 * NT];

        // complete output row r-1 with this row's bottom-tap contribution
        float4 d0 = am0, d1 = am1;
        hconv(d0, d1, Wt[2][0], Wt[2][1], Wt[2][2], cur);
        if (i >= 2) {             // output rows hs .. hs+HC-1
            float4* po = ob + (size_t)(r - 1) * ROWF4;
            po[0]  = d0;
            po[CQ] = d1;
        }

        // roll accumulators: am <- ac + middle-tap, ac <- top-tap (fresh)
        am0 = ac0; am1 = ac1;
        hconv(am0, am1, Wt[1][0], Wt[1][1], Wt[1][2], cur);
        ac0 = z; ac1 = z;
        hconv(ac0, ac1, Wt[0][0], Wt[0][1], Wt[0][2], cur);

        // refill slot with row r+6 (consumed at i+6), or an empty group in the
        // tail so the per-iteration group count stays exactly one.
        if (i <= HC - 5)
            load_async(r + 6, slot);
        else
            cp_commit();
    }
}

extern "C" void kernel_launch(void* const* d_in, const int* in_sizes, int n_in,
                              void* d_out, int out_size)
{
    const float4* x   = (const float4*)d_in[0];
    const float*  krn = (const float*)d_in[1];
    float4*       out = (float4*)d_out;

    cudaFuncSetAttribute(contour_kernel,
                         cudaFuncAttributeMaxDynamicSharedMemorySize, SMEM_BYTES);

    dim3 block(CG, W_ / 2, 1);               // 224 threads
    dim3 grid(C_ / (CG * 4), H_ / HC, B_);   // 8 x 4 x 32 = 1024 blocks
    contour_kernel<<<grid, block, SMEM_BYTES>>>(x, krn, out);
}

// round 9
// speedup vs baseline: 4.1144x; 4.1144x over previous
#include <cuda_runtime.h>

// ContourIntegrationLayer: depthwise 3x3 conv (center tap zeroed) + residual.
// x: [B=32, H=56, W=56, C=256] fp32 NHWC, kernel: [3,3,256] fp32.
// Residual folded by forcing the center weight to 1.0.
//
// Round 9: Round-5 design (confirmed optimum: 4-slot register row ring,
// 3 rows / 12 LDG.128 in flight, 224 threads, occ 2, 1024 blocks, no SMEM,
// no syncs) + streaming stores (__stcs: output written once, never read ->
// keep L2 for input halo reuse) + ring prolog LDGs issued before weight LDGs.

#define B_  32
#define H_  56
#define W_  56
#define C_  256
#define CG  8
#define HC  14                   // output rows per block
#define CQ  (C_ / 4)             // 64 float4 per pixel
#define ROWF4 (W_ * CQ)          // 3584 float4 per image row

__global__ __launch_bounds__(224, 2)
void contour_kernel(const float4* __restrict__ x,
                    const float*  __restrict__ krn,
                    float4*       __restrict__ out)
{
    const int tx  = threadIdx.x;     // 0..7  channel group
    const int ty  = threadIdx.y;     // 0..27 w-pair
    const int cb  = blockIdx.x;      // 0..7  channel block
    const int hch = blockIdx.y;      // 0..3  H chunk
    const int b   = blockIdx.z;      // 0..31 batch
    const int c   = cb * 32 + tx * 4;

    const int  w0  = ty * 2;
    const bool wlo = (w0 > 0);           // col w0-1 exists
    const bool whi = (w0 + 2 < W_);      // col w1+1 exists
    const float4 z = make_float4(0.f, 0.f, 0.f, 0.f);

    const size_t base = (size_t)b * H_ * ROWF4 + (size_t)w0 * CQ + cb * CG + tx;
    const float4* xb = x   + base;
    float4*       ob = out + base;

    const int hs = hch * HC;

    // row loader: cols w0-1, w0, w0+1, w0+2 of input row r (zeros OOB)
    auto load = [&](int r, float4* v) {
        if ((unsigned)r < (unsigned)H_) {
            const float4* p = xb + (size_t)r * ROWF4;
            v[0] = wlo ? p[-CQ]    : z;
            v[1] = p[0];
            v[2] = p[CQ];
            v[3] = whi ? p[2 * CQ] : z;
        } else {
            v[0] = z; v[1] = z; v[2] = z; v[3] = z;
        }
    };

    float4 buf[4][4];               // 4-slot register row ring

    // prolog ring loads FIRST: rows hs-1 .. hs+2 (16 LDG back-to-back,
    // start the DRAM round-trip before anything else)
    load(hs - 1, buf[0]);
    load(hs,     buf[1]);
    load(hs + 1, buf[2]);
    load(hs + 2, buf[3]);

    // 3x3 per-channel weights; center tap := 1.0 (residual fold).
    // Loaded after the ring prolog: consumed later, off the critical path.
    float4 Wt[3][3];
#pragma unroll
    for (int ky = 0; ky < 3; ky++)
#pragma unroll
        for (int kx = 0; kx < 3; kx++)
            Wt[ky][kx] = *reinterpret_cast<const float4*>(krn + (ky * 3 + kx) * C_ + c);
    Wt[1][1] = make_float4(1.f, 1.f, 1.f, 1.f);

    // horizontal conv of v[0..3] with weight row k, accumulated into (o0,o1)
    auto hconv = [&](float4& o0, float4& o1, const float4 k0, const float4 k1,
                     const float4 k2, const float4* v) {
        o0.x = fmaf(k0.x, v[0].x, fmaf(k1.x, v[1].x, fmaf(k2.x, v[2].x, o0.x)));
        o0.y = fmaf(k0.y, v[0].y, fmaf(k1.y, v[1].y, fmaf(k2.y, v[2].y, o0.y)));
        o0.z = fmaf(k0.z, v[0].z, fmaf(k1.z, v[1].z, fmaf(k2.z, v[2].z, o0.z)));
        o0.w = fmaf(k0.w, v[0].w, fmaf(k1.w, v[1].w, fmaf(k2.w, v[2].w, o0.w)));
        o1.x = fmaf(k0.x, v[1].x, fmaf(k1.x, v[2].x, fmaf(k2.x, v[3].x, o1.x)));
        o1.y = fmaf(k0.y, v[1].y, fmaf(k1.y, v[2].y, fmaf(k2.y, v[3].y, o1.y)));
        o1.z = fmaf(k0.z, v[1].z, fmaf(k1.z, v[2].z, fmaf(k2.z, v[3].z, o1.z)));
        o1.w = fmaf(k0.w, v[1].w, fmaf(k1.w, v[2].w, fmaf(k2.w, v[3].w, o1.w)));
    };

    float4 am0 = z, am1 = z;        // partial accum for output row r-1
    float4 ac0 = z, ac1 = z;        // partial accum for output row r

    // iterations i = 0..HC+1 consume input rows hs-1 .. hs+HC
#pragma unroll
    for (int i = 0; i < HC + 2; i++) {
        const int r = hs - 1 + i;
        const float4* cur = buf[i % 4];

        // complete output row r-1 with this row's bottom-tap contribution
        float4 d0 = am0, d1 = am1;
        hconv(d0, d1, Wt[2][0], Wt[2][1], Wt[2][2], cur);
        if (i >= 2) {               // output rows hs .. hs+HC-1
            float4* po = ob + (size_t)(r - 1) * ROWF4;
            __stcs(po,      d0);    // streaming: written once, never read
            __stcs(po + CQ, d1);
        }

        // roll accumulators: am <- ac + middle-tap, ac <- top-tap (fresh)
        am0 = ac0; am1 = ac1;
        hconv(am0, am1, Wt[1][0], Wt[1][1], Wt[1][2], cur);
        ac0 = z; ac1 = z;
        hconv(ac0, ac1, Wt[0][0], Wt[0][1], Wt[0][2], cur);

        // refill the slot just consumed with row r+4 (consumed at i+4)
        if (i <= HC - 3)
            load(r + 4, buf[i % 4]);
    }
}

extern "C" void kernel_launch(void* const* d_in, const int* in_sizes, int n_in,
                              void* d_out, int out_size)
{
    const float4* x   = (const float4*)d_in[0];
    const float*  krn = (const float*)d_in[1];
    float4*       out = (float4*)d_out;

    dim3 block(CG, W_ / 2, 1);               // 224 threads
    dim3 grid(C_ / (CG * 4), H_ / HC, B_);   // 8 x 4 x 32 = 1024 blocks
    contour_kernel<<<grid, block>>>(x, krn, out);
}

// round 10
// speedup vs baseline: 4.1617x; 1.0115x over previous
#include <cuda_runtime.h>

// ContourIntegrationLayer: depthwise 3x3 conv (center tap zeroed) + residual.
// x: [B=32, H=56, W=56, C=256] fp32 NHWC, kernel: [3,3,256] fp32.
// Residual folded by forcing the center weight to 1.0.
//
// Round 10: Round-9 design (4-slot register row ring, 3 rows / 12 LDG.128 in
// flight, 224 threads, occ 2, 1024 blocks, __stcs stores, no SMEM, no syncs)
// with all convolution FMAs rewritten as packed fma.rn.f32x2 (FFMA2):
// 96 FFMA/iter -> 48 FFMA2/iter, shrinking the compute phase of each
// iteration so the DRAM duty cycle rises. float4 data is viewed as 2x f32x2
// (bit-identical; LDG.128/STG.128 unchanged, no pack/unpack).

#define B_  32
#define H_  56
#define W_  56
#define C_  256
#define CG  8
#define HC  14                   // output rows per block
#define CQ  (C_ / 4)             // 64 float4 per pixel
#define ROWF4 (W_ * CQ)          // 3584 float4 per image row

struct __align__(16) P2 { unsigned long long lo, hi; };   // float4 as 2x f32x2

__device__ __forceinline__ void fma2(unsigned long long& o,
                                     unsigned long long a,
                                     unsigned long long b)
{
    asm("fma.rn.f32x2 %0, %1, %2, %0;" : "+l"(o) : "l"(a), "l"(b));
}

__global__ __launch_bounds__(224, 2)
void contour_kernel(const float4* __restrict__ x,
                    const float*  __restrict__ krn,
                    float4*       __restrict__ out)
{
    const int tx  = threadIdx.x;     // 0..7  channel group
    const int ty  = threadIdx.y;     // 0..27 w-pair
    const int cb  = blockIdx.x;      // 0..7  channel block
    const int hch = blockIdx.y;      // 0..3  H chunk
    const int b   = blockIdx.z;      // 0..31 batch
    const int c   = cb * 32 + tx * 4;

    const int  w0  = ty * 2;
    const bool wlo = (w0 > 0);           // col w0-1 exists
    const bool whi = (w0 + 2 < W_);      // col w1+1 exists
    const P2 z2 = {0ull, 0ull};

    const size_t base = (size_t)b * H_ * ROWF4 + (size_t)w0 * CQ + cb * CG + tx;
    const P2* xb = reinterpret_cast<const P2*>(x) + base;
    float4*   ob = reinterpret_cast<float4*>(
                       reinterpret_cast<P2*>(out) + base) - 0;  // same index space
    P2*       obp = reinterpret_cast<P2*>(out) + base;

    const int hs = hch * HC;

    // row loader: cols w0-1, w0, w0+1, w0+2 of input row r (zeros OOB)
    auto load = [&](int r, P2* v) {
        if ((unsigned)r < (unsigned)H_) {
            const P2* p = xb + (size_t)r * ROWF4;
            v[0] = wlo ? p[-CQ]    : z2;
            v[1] = p[0];
            v[2] = p[CQ];
            v[3] = whi ? p[2 * CQ] : z2;
        } else {
            v[0] = z2; v[1] = z2; v[2] = z2; v[3] = z2;
        }
    };

    P2 buf[4][4];                   // 4-slot register row ring

    // prolog ring loads FIRST: rows hs-1 .. hs+2 (16 LDG back-to-back)
    load(hs - 1, buf[0]);
    load(hs,     buf[1]);
    load(hs + 1, buf[2]);
    load(hs + 2, buf[3]);

    // 3x3 per-channel weights; center tap := 1.0 (residual fold)
    P2 Wt[3][3];
#pragma unroll
    for (int ky = 0; ky < 3; ky++)
#pragma unroll
        for (int kx = 0; kx < 3; kx++)
            Wt[ky][kx] = *reinterpret_cast<const P2*>(krn + (ky * 3 + kx) * C_ + c);
    Wt[1][1].lo = 0x3f8000003f800000ull;     // {1.0f, 1.0f}
    Wt[1][1].hi = 0x3f8000003f800000ull;

    // horizontal conv of v[0..3] with weight row k, accumulated into (o0,o1)
    // 12 fma.rn.f32x2 per call (was 24 FFMA)
    auto hconv = [&](P2& o0, P2& o1, const P2 k0, const P2 k1, const P2 k2,
                     const P2* v) {
        fma2(o0.lo, k0.lo, v[0].lo); fma2(o0.hi, k0.hi, v[0].hi);
        fma2(o0.lo, k1.lo, v[1].lo); fma2(o0.hi, k1.hi, v[1].hi);
        fma2(o0.lo, k2.lo, v[2].lo); fma2(o0.hi, k2.hi, v[2].hi);
        fma2(o1.lo, k0.lo, v[1].lo); fma2(o1.hi, k0.hi, v[1].hi);
        fma2(o1.lo, k1.lo, v[2].lo); fma2(o1.hi, k1.hi, v[2].hi);
        fma2(o1.lo, k2.lo, v[3].lo); fma2(o1.hi, k2.hi, v[3].hi);
    };

    P2 am0 = z2, am1 = z2;          // partial accum for output row r-1
    P2 ac0 = z2, ac1 = z2;          // partial accum for output row r

    // iterations i = 0..HC+1 consume input rows hs-1 .. hs+HC
#pragma unroll
    for (int i = 0; i < HC + 2; i++) {
        const int r = hs - 1 + i;
        const P2* cur = buf[i % 4];

        // complete output row r-1 with this row's bottom-tap contribution
        P2 d0 = am0, d1 = am1;
        hconv(d0, d1, Wt[2][0], Wt[2][1], Wt[2][2], cur);
        if (i >= 2) {               // output rows hs .. hs+HC-1
            P2* po = obp + (size_t)(r - 1) * ROWF4;
            __stcs(reinterpret_cast<float4*>(po),
                   *reinterpret_cast<const float4*>(&d0));
            __stcs(reinterpret_cast<float4*>(po + CQ),
                   *reinterpret_cast<const float4*>(&d1));
        }

        // roll accumulators: am <- ac + middle-tap, ac <- top-tap (fresh)
        am0 = ac0; am1 = ac1;
        hconv(am0, am1, Wt[1][0], Wt[1][1], Wt[1][2], cur);
        ac0 = z2; ac1 = z2;
        hconv(ac0, ac1, Wt[0][0], Wt[0][1], Wt[0][2], cur);

        // refill the slot just consumed with row r+4 (consumed at i+4)
        if (i <= HC - 3)
            load(r + 4, buf[i % 4]);
    }
    (void)ob;
}

extern "C" void kernel_launch(void* const* d_in, const int* in_sizes, int n_in,
                              void* d_out, int out_size)
{
    const float4* x   = (const float4*)d_in[0];
    const float*  krn = (const float*)d_in[1];
    float4*       out = (float4*)d_out;

    dim3 block(CG, W_ / 2, 1);               // 224 threads
    dim3 grid(C_ / (CG * 4), H_ / HC, B_);   // 8 x 4 x 32 = 1024 blocks
    contour_kernel<<<grid, block>>>(x, krn, out);
}